// round 4
// baseline (speedup 1.0000x reference)
#include <cuda_runtime.h>
#include <cuda_bf16.h>

#define PI_D 3.14159265358979323846
#define PI_F 3.14159265358979f
#define DNUM 729
#define DPAD 732
#define ANUM 180
#define HNUM 512
#define WNUM 512
#define NPIX (HNUM * WNUM)
#define BNUM 2
#define CHUNK 244

// ---------------- device scratch ----------------
__device__ float g_h[DNUM];
__device__ float g_cos[ANUM];
__device__ float g_sin[ANUM];
__device__ float2 g_filt2[ANUM * DPAD];   // (batch0, batch1) interleaved
__device__ float g_pre0[BNUM][ANUM];
__device__ float g_pre728[BNUM][ANUM];
__device__ unsigned int g_max_bits;

// ---------------- f32x2 helpers ----------------
__device__ __forceinline__ unsigned long long dup2(float f) {
    unsigned long long r;
    asm("mov.b64 %0, {%1, %1};" : "=l"(r) : "f"(f));
    return r;
}
__device__ __forceinline__ void ffma2(unsigned long long& d,
                                      unsigned long long a,
                                      unsigned long long b) {
    asm("fma.rn.f32x2 %0, %1, %2, %0;" : "+l"(d) : "l"(a), "l"(b));
}
__device__ __forceinline__ void unpack2(unsigned long long v, float& lo, float& hi) {
    asm("mov.b64 {%0, %1}, %2;" : "=f"(lo), "=f"(hi) : "l"(v));
}

// ---------------- kernel 1: init h, cos/sin, reset max ----------------
__global__ void fbp_init_kernel() {
    int j = blockIdx.x;
    int l = threadIdx.x;
    if (j == 0 && l == 0) g_max_bits = 0u;
    if (j < ANUM && l == 0) {
        double ang = (double)j * (PI_D / 179.0);
        g_cos[j] = (float)cos(ang);
        g_sin[j] = (float)sin(ang);
    }
    const float C2 = (float)(2.0 * PI_D / 729.0);
    const float NI = (float)(-1.0 / (PI_D * PI_D));
    float acc = 0.0f;
    for (int k = 1 + 2 * l; k < DNUM; k += 64) {
        int r = (k * j) % DNUM;
        float coef = NI / ((float)k * (float)k);
        acc += coef * cosf((float)r * C2);
    }
    #pragma unroll
    for (int o = 16; o; o >>= 1) acc += __shfl_xor_sync(0xffffffffu, acc, o);
    if (l == 0) g_h[j] = (0.25f + acc) * (1.0f / 729.0f);
}

// ---------------- kernel 2: filter, f32x2-packed batch pair --------------
// grid <<<540, 64>>> : block = (angle a, n-chunk of 244); rows b=0 & b=1 packed.
__global__ void fbp_filter_kernel(const float* __restrict__ sino) {
    __shared__ __align__(16) float2 s2[736];
    __shared__ __align__(16) float s_h[1472];  // s_h[i] = h[(i-735) mod 729]
    int tid = threadIdx.x;
    int blk = blockIdx.x;
    int a = blk / 3;
    int chunk = blk - 3 * a;
    const float* r0 = sino + a * DNUM;
    const float* r1 = sino + (ANUM + a) * DNUM;
    for (int i = tid; i < 736; i += 64) {
        float v0 = (i < DNUM) ? __ldg(r0 + i) : 0.0f;
        float v1 = (i < DNUM) ? __ldg(r1 + i) : 0.0f;
        s2[i] = make_float2(v0, v1);
    }
    for (int i = tid; i < 1472; i += 64) {
        int j = i - 6;
        if (j < 0) j += 729;
        if (j >= 729) j -= 729;
        if (j >= 729) j -= 729;
        s_h[i] = g_h[j];
    }
    __syncthreads();

    if (tid < 61) {
        int n0 = chunk * CHUNK + 4 * tid;
        unsigned long long ac0 = 0ull, ac1 = 0ull, ac2 = 0ull, ac3 = 0ull;
        const double* sd = reinterpret_cast<const double*>(s2);
        #pragma unroll 2
        for (int g = 0; g < 92; ++g) {
            int m0 = 8 * g;
            double2 sA = *reinterpret_cast<const double2*>(sd + m0);
            double2 sB = *reinterpret_cast<const double2*>(sd + m0 + 2);
            double2 sC = *reinterpret_cast<const double2*>(sd + m0 + 4);
            double2 sD = *reinterpret_cast<const double2*>(sd + m0 + 6);
            unsigned long long k0 = __double_as_longlong(sA.x);
            unsigned long long k1 = __double_as_longlong(sA.y);
            unsigned long long k2 = __double_as_longlong(sB.x);
            unsigned long long k3 = __double_as_longlong(sB.y);
            unsigned long long k4 = __double_as_longlong(sC.x);
            unsigned long long k5 = __double_as_longlong(sC.y);
            unsigned long long k6 = __double_as_longlong(sD.x);
            unsigned long long k7 = __double_as_longlong(sD.y);
            int L = n0 - m0 + 728;
            float4 h0 = *reinterpret_cast<const float4*>(s_h + L);
            float4 h1 = *reinterpret_cast<const float4*>(s_h + L + 4);
            float4 h2 = *reinterpret_cast<const float4*>(s_h + L + 8);
            unsigned long long H0 = dup2(h0.x), H1 = dup2(h0.y);
            unsigned long long H2 = dup2(h0.z), H3 = dup2(h0.w);
            unsigned long long H4 = dup2(h1.x), H5 = dup2(h1.y);
            unsigned long long H6 = dup2(h1.z), H7 = dup2(h1.w);
            unsigned long long H8 = dup2(h2.x), H9 = dup2(h2.y);
            unsigned long long H10 = dup2(h2.z);
            ffma2(ac0, k0, H7);  ffma2(ac1, k0, H8);  ffma2(ac2, k0, H9);  ffma2(ac3, k0, H10);
            ffma2(ac0, k1, H6);  ffma2(ac1, k1, H7);  ffma2(ac2, k1, H8);  ffma2(ac3, k1, H9);
            ffma2(ac0, k2, H5);  ffma2(ac1, k2, H6);  ffma2(ac2, k2, H7);  ffma2(ac3, k2, H8);
            ffma2(ac0, k3, H4);  ffma2(ac1, k3, H5);  ffma2(ac2, k3, H6);  ffma2(ac3, k3, H7);
            ffma2(ac0, k4, H3);  ffma2(ac1, k4, H4);  ffma2(ac2, k4, H5);  ffma2(ac3, k4, H6);
            ffma2(ac0, k5, H2);  ffma2(ac1, k5, H3);  ffma2(ac2, k5, H4);  ffma2(ac3, k5, H5);
            ffma2(ac0, k6, H1);  ffma2(ac1, k6, H2);  ffma2(ac2, k6, H3);  ffma2(ac3, k6, H4);
            ffma2(ac0, k7, H0);  ffma2(ac1, k7, H1);  ffma2(ac2, k7, H2);  ffma2(ac3, k7, H3);
        }
        float o00, o01, o02, o03, o10, o11, o12, o13;
        unpack2(ac0, o00, o10);
        unpack2(ac1, o01, o11);
        unpack2(ac2, o02, o12);
        unpack2(ac3, o03, o13);
        // interleaved (b0,b1) store: two float4 = four float2 pairs
        float4* fo = reinterpret_cast<float4*>(g_filt2 + a * DPAD + n0);
        fo[0] = make_float4(o00, o10, o01, o11);
        fo[1] = make_float4(o02, o12, o03, o13);
    }
}

// ---------------- kernel 3: prefix sums of cols 0 and 728 ---------------
__global__ void fbp_prefix_kernel() {
    int w = threadIdx.x >> 5;
    int l = threadIdx.x & 31;
    int b = w >> 1;
    int col = (w & 1) ? 728 : 0;
    const float* base = reinterpret_cast<const float*>(g_filt2 + col) + b;
    float* outp = (w & 1) ? g_pre728[b] : g_pre0[b];
    float carry = 0.0f;
    #pragma unroll
    for (int c = 0; c < 6; ++c) {
        int a = c * 32 + l;
        float v = (a < 179) ? base[a * (DPAD * 2)] : 0.0f;
        float s = v;
        #pragma unroll
        for (int off = 1; off < 32; off <<= 1) {
            float t = __shfl_up_sync(0xffffffffu, s, off);
            if (l >= off) s += t;
        }
        if (a < ANUM) outp[a] = carry + s - v;
        carry += __shfl_sync(0xffffffffu, s, 31);
    }
}

// ---------------- kernel 4: backprojection, both batches per thread ------
// grid <<<1024, 256>>> : one thread per pixel (both batches).
__global__ void fbp_backproject_kernel(float* __restrict__ out) {
    __shared__ float2 s_cs[ANUM];             // (cos*K, sin*K)
    __shared__ float s_p0[BNUM][ANUM], s_p728[BNUM][ANUM];
    __shared__ float red[8];
    int tid = threadIdx.x;
    const float KIDX = (float)(729.0 / (2.0 * PI_D));
    if (tid < ANUM)
        s_cs[tid] = make_float2(g_cos[tid] * KIDX, g_sin[tid] * KIDX);
    for (int i = tid; i < 2 * ANUM; i += 256) {
        int b = i / ANUM, a = i - b * ANUM;
        s_p0[b][a] = g_pre0[b][a];
        s_p728[b][a] = g_pre728[b][a];
    }
    __syncthreads();

    int p = (blockIdx.x << 8) | tid;
    int y = p >> 9;
    int x = p & 511;
    float xc = (float)x - 256.0f;
    float yc = (float)y - 256.0f;
    const float2* __restrict__ g2 = g_filt2;

    float d2 = xc * xc + yc * yc;
    int lo, hi, acfl = 0;
    if (d2 < 256.0f) {
        lo = 0; hi = 178;
    } else {
        // fast atan2(-xc, yc) -> acf in [0, 179]; err <= ~0.04 steps
        float u = -xc, v = yc;
        float ax = fabsf(u), av = fabsf(v);
        float z = __fdividef(fminf(ax, av), fmaxf(ax, av));
        float z2 = z * z;
        float t = z * fmaf(z2, fmaf(z2, 0.0793313f, -0.2886790f), 0.9953540f);
        if (ax > av) t = 1.57079632679f - t;
        if (v < 0.0f) t = PI_F - t;
        float th = (u < 0.0f) ? -t : t;
        float acf = th * (179.0f / PI_F);
        if (acf < 0.0f) acf += 179.0f;
        acfl = (int)acf;
        int half = 6 + (int)(375.0f * rsqrtf(d2));   // +1 vs ceil-based window
        lo = acfl - half;
        hi = acfl + half;
    }

    float acc0 = 0.0f, acc1 = 0.0f;
    #pragma unroll 1
    for (int uu = lo; uu <= hi; ++uu) {
        int a = uu;
        if (a < 0) a += 179;
        else if (a > 178) a -= 179;
        float2 cs = s_cs[a];
        float rs = fmaf(xc, cs.x, yc * cs.y);
        rs = fminf(fmaxf(rs, 0.0f), 728.0f);
        float2 f = __ldg(g2 + a * DPAD + (int)rs);
        acc0 += f.x;
        acc1 += f.y;
    }
    {   // leftover angle 179, always exact
        float2 cs = s_cs[179];
        float rs = fmaf(xc, cs.x, yc * cs.y);
        rs = fminf(fmaxf(rs, 0.0f), 728.0f);
        float2 f = __ldg(g2 + 179 * DPAD + (int)rs);
        acc0 += f.x;
        acc1 += f.y;
    }

    // complement intervals (u-space complement [hi+1, lo+178])
    int i1lo = hi + 1, i1hi = min(178, lo + 178);
    int i2lo = max(0, hi - 178), i2hi = lo - 1;
    if (i1lo <= i1hi || i2lo <= i2hi) {
        int um = acfl + 90;                  // strictly inside (acf, acf+179)
        float sR;
        if (um <= 178) {
            float2 cs = s_cs[um];
            sR = fmaf(xc, cs.x, yc * cs.y);
        } else {
            float2 cs = s_cs[um - 179];
            sR = -fmaf(xc, cs.x, yc * cs.y);
        }
        bool pos = sR > 0.0f;
        if (i1lo <= i1hi) {
            if (pos) {
                acc0 += s_p728[0][i1hi + 1] - s_p728[0][i1lo];
                acc1 += s_p728[1][i1hi + 1] - s_p728[1][i1lo];
            } else {
                acc0 += s_p0[0][i1hi + 1] - s_p0[0][i1lo];
                acc1 += s_p0[1][i1hi + 1] - s_p0[1][i1lo];
            }
        }
        if (i2lo <= i2hi) {
            if (pos) {
                acc0 += s_p0[0][i2hi + 1] - s_p0[0][i2lo];
                acc1 += s_p0[1][i2hi + 1] - s_p0[1][i2lo];
            } else {
                acc0 += s_p728[0][i2hi + 1] - s_p728[0][i2lo];
                acc1 += s_p728[1][i2hi + 1] - s_p728[1][i2lo];
            }
        }
    }

    float v0 = acc0 * (float)(PI_D / 180.0);
    float v1 = acc1 * (float)(PI_D / 180.0);
    out[p] = fmaxf(v0, 0.0f);
    out[NPIX + p] = fmaxf(v1, 0.0f);

    float m = fmaxf(v0, v1);
    #pragma unroll
    for (int o = 16; o; o >>= 1) m = fmaxf(m, __shfl_xor_sync(0xffffffffu, m, o));
    if ((tid & 31) == 0) red[tid >> 5] = m;
    __syncthreads();
    if (tid == 0) {
        #pragma unroll
        for (int w = 1; w < 8; w++) m = fmaxf(m, red[w]);
        unsigned uu = __float_as_uint(m);
        unsigned key = (uu & 0x80000000u) ? ~uu : (uu | 0x80000000u);
        atomicMax(&g_max_bits, key);
    }
}

// ---------------- kernel 5: fallback fill when global max < 0 ------------
__global__ void fbp_clip_kernel(float* __restrict__ out) {
    unsigned key = g_max_bits;
    if (key & 0x80000000u) return;
    float M = __uint_as_float(~key);
    for (int i = blockIdx.x * 256 + threadIdx.x; i < BNUM * NPIX; i += gridDim.x * 256)
        out[i] = M;
}

// --------------------------------------------------------------------------
extern "C" void kernel_launch(void* const* d_in, const int* in_sizes, int n_in,
                              void* d_out, int out_size) {
    (void)in_sizes; (void)n_in; (void)out_size;
    const float* sino = (const float*)d_in[0];
    float* out = (float*)d_out;

    fbp_init_kernel<<<DNUM, 32>>>();
    fbp_filter_kernel<<<540, 64>>>(sino);
    fbp_prefix_kernel<<<1, 128>>>();
    fbp_backproject_kernel<<<1024, 256>>>(out);
    fbp_clip_kernel<<<148, 256>>>(out);
}